// round 15
// baseline (speedup 1.0000x reference)
#include <cuda_runtime.h>
#include <cuda_bf16.h>
#include <cstdint>

#define BS 4
#define NQ 16384
#define EMB 128
#define NH 8
#define NP 4
#define HD 16
#define BEV 128
#define M_TOTAL (BS * NQ)   // 65536

// Scratch (device globals: allocation-guard safe)
__device__ __nv_bfloat16 g_value[M_TOTAL * EMB];    // head-major: ((b*8+h)*NQ+q)*16+d
__device__ float         g_offattn[M_TOTAL * 96];   // ((b*8+h)*NQ+q)*12 : 8 off + 4 logits
__device__ __nv_bfloat16 g_Wval16[128 * 128];
__device__ __nv_bfloat16 g_Wout16[128 * 128];
__device__ __nv_bfloat16 g_Wcat16[128 * 96];        // [W_off | W_attn]

// ---------------------------------------------------------------------------
// helpers
// ---------------------------------------------------------------------------
__device__ __forceinline__ uint32_t smem_u32(const void* p) {
    return (uint32_t)__cvta_generic_to_shared(p);
}
__device__ __forceinline__ void ldsm_x4(uint32_t& r0, uint32_t& r1, uint32_t& r2,
                                        uint32_t& r3, uint32_t addr) {
    asm volatile("ldmatrix.sync.aligned.m8n8.x4.shared.b16 {%0,%1,%2,%3},[%4];\n"
                 : "=r"(r0), "=r"(r1), "=r"(r2), "=r"(r3) : "r"(addr));
}
__device__ __forceinline__ void ldsm_x4t(uint32_t& r0, uint32_t& r1, uint32_t& r2,
                                         uint32_t& r3, uint32_t addr) {
    asm volatile("ldmatrix.sync.aligned.m8n8.x4.trans.shared.b16 {%0,%1,%2,%3},[%4];\n"
                 : "=r"(r0), "=r"(r1), "=r"(r2), "=r"(r3) : "r"(addr));
}
__device__ __forceinline__ void mma_bf16(float* d, const uint32_t* a,
                                         const uint32_t* b) {
    asm volatile(
        "mma.sync.aligned.m16n8k16.row.col.f32.bf16.bf16.f32 "
        "{%0,%1,%2,%3},{%4,%5,%6,%7},{%8,%9},{%0,%1,%2,%3};\n"
        : "+f"(d[0]), "+f"(d[1]), "+f"(d[2]), "+f"(d[3])
        : "r"(a[0]), "r"(a[1]), "r"(a[2]), "r"(a[3]), "r"(b[0]), "r"(b[1]));
}
__device__ __forceinline__ void cp_async16(uint32_t saddr, const void* g) {
    asm volatile("cp.async.ca.shared.global [%0], [%1], 16;\n" :: "r"(saddr), "l"(g));
}
__device__ __forceinline__ void cp_commit() {
    asm volatile("cp.async.commit_group;\n" ::: "memory");
}
__device__ __forceinline__ void cp_wait_all() {
    asm volatile("cp.async.wait_group 0;\n" ::: "memory");
}

#define AST 136    // A / Wval smem row stride (bf16)
#define WST64 72   // W half-tile smem row stride (bf16)

// ---------------------------------------------------------------------------
// One-shot weight conversion fp32 -> bf16 (+ pack W_off|W_attn)
// ---------------------------------------------------------------------------
__global__ __launch_bounds__(256) void conv_kernel(
    const float* __restrict__ W_val, const float* __restrict__ W_out,
    const float* __restrict__ W_off, const float* __restrict__ W_attn)
{
    const int i = blockIdx.x * 256 + threadIdx.x;   // 176 blocks
    if (i < 16384) {
        g_Wval16[i] = __float2bfloat16(W_val[i]);
        g_Wout16[i] = __float2bfloat16(W_out[i]);
    } else {
        const int j = i - 16384;
        if (j < 12288) {
            const int k = j / 96, c = j % 96;
            const float v = (c < 64) ? W_off[k * 64 + c] : W_attn[k * 32 + (c - 64)];
            g_Wcat16[j] = __float2bfloat16(v);
        }
    }
}

// ---------------------------------------------------------------------------
// Fused projection kernel: 64-row one-shot tile per CTA.
//   1) value = q @ W_val + b_val          -> g_value (bf16 head-major)
//   2) offattn = q @ [W_off|W_attn] + b   -> g_offattn (12 fp32 per (b,h,q))
// ---------------------------------------------------------------------------
__global__ __launch_bounds__(256) void proj_kernel(
    const float* __restrict__ query,
    const float* __restrict__ b_val,
    const float* __restrict__ b_off, const float* __restrict__ b_attn)
{
    __shared__ __nv_bfloat16 As[64 * AST];
    __shared__ __nv_bfloat16 Ws[128 * AST];

    const int t = threadIdx.x;
    const int rowBase = blockIdx.x * 64;
    const uint32_t asb = smem_u32(As);
    const uint32_t wsb = smem_u32(Ws);

    // --- W_val tile via cp.async (2048 x 16B) ---
#pragma unroll
    for (int j = 0; j < 8; j++) {
        const int idx = t + j * 256;
        const int row = idx >> 4, c8 = idx & 15;
        cp_async16(wsb + (row * AST + c8 * 8) * 2, g_Wval16 + row * 128 + c8 * 8);
    }
    cp_commit();

    // --- A tile: 64x128 fp32 -> bf16 (overlaps cp.async) ---
#pragma unroll
    for (int j = 0; j < 8; j++) {
        const int idx = t + j * 256;
        const int row = idx >> 5, c4 = idx & 31;
        float4 v = *(const float4*)(query + (size_t)(rowBase + row) * EMB + c4 * 4);
        *(__nv_bfloat162*)(As + row * AST + c4 * 4)     = __floats2bfloat162_rn(v.x, v.y);
        *(__nv_bfloat162*)(As + row * AST + c4 * 4 + 2) = __floats2bfloat162_rn(v.z, v.w);
    }
    cp_wait_all();
    __syncthreads();

    const int wid = t >> 5, lane = t & 31;
    const int wm = wid & 3, wn = wid >> 2;
    const int m0 = wm * 16;
    const uint32_t aAddr = asb + ((m0 + (lane & 15)) * AST + (lane >> 4) * 8) * 2;
    const int kOff = ((lane >> 3) & 1) * 8 + (lane & 7);
    const int cOff = ((lane >> 4) & 1) * 8;
    const int lr = lane >> 2, lc = (lane & 3) * 2;

    // ===== part 1: value (N=128, warp n-tile 64, NF=8) =====
    float acc[8][4];
    {
        const int n0 = wn * 64;
#pragma unroll
        for (int nf = 0; nf < 8; nf++)
#pragma unroll
            for (int i = 0; i < 4; i++) acc[nf][i] = 0.0f;
        uint32_t bAddr[4];
#pragma unroll
        for (int np = 0; np < 4; np++)
            bAddr[np] = wsb + (kOff * AST + n0 + np * 16 + cOff) * 2;

#pragma unroll
        for (int kk = 0; kk < 8; kk++) {
            uint32_t a[4];
            ldsm_x4(a[0], a[1], a[2], a[3], aAddr + kk * 32);
            uint32_t b[8][2];
#pragma unroll
            for (int np = 0; np < 4; np++)
                ldsm_x4t(b[2 * np][0], b[2 * np][1], b[2 * np + 1][0], b[2 * np + 1][1],
                         bAddr[np] + kk * 16 * AST * 2);
#pragma unroll
            for (int nf = 0; nf < 8; nf++) mma_bf16(acc[nf], a, b[nf]);
        }
    }
    __syncthreads();   // all warps done reading Ws

    // --- issue W_cat cp.async (1536 x 16B), then do part-1 epilogue ---
    constexpr int WSTc = 104;
#pragma unroll
    for (int j = 0; j < 6; j++) {
        const int idx = t + j * 256;
        const int row = idx / 12, c8 = idx % 12;
        cp_async16(wsb + (row * WSTc + c8 * 8) * 2, g_Wcat16 + row * 96 + c8 * 8);
    }
    cp_commit();

    {
        const int n0 = wn * 64;
        const int row = rowBase + m0 + lr;
        const int b0 = row >> 14, q0 = row & 16383;
#pragma unroll
        for (int nf = 0; nf < 8; nf++) {
            const int col = n0 + nf * 8 + lc;
            const float2 bb = *(const float2*)(b_val + col);
            const int h = col >> 4, d = col & 15;
            const size_t base = (size_t)(b0 * 8 + h) * NQ;
            *(__nv_bfloat162*)(g_value + (base + q0) * 16 + d) =
                __floats2bfloat162_rn(acc[nf][0] + bb.x, acc[nf][1] + bb.y);
            *(__nv_bfloat162*)(g_value + (base + q0 + 8) * 16 + d) =
                __floats2bfloat162_rn(acc[nf][2] + bb.x, acc[nf][3] + bb.y);
        }
    }
    cp_wait_all();
    __syncthreads();

    // ===== part 2: offattn (N=96, warp n-tile 48, NF=6) =====
    {
        const int n0 = wn * 48;
        float ac2[6][4];
#pragma unroll
        for (int nf = 0; nf < 6; nf++)
#pragma unroll
            for (int i = 0; i < 4; i++) ac2[nf][i] = 0.0f;
        uint32_t bAddr[3];
#pragma unroll
        for (int np = 0; np < 3; np++)
            bAddr[np] = wsb + (kOff * WSTc + n0 + np * 16 + cOff) * 2;

#pragma unroll
        for (int kk = 0; kk < 8; kk++) {
            uint32_t a[4];
            ldsm_x4(a[0], a[1], a[2], a[3], aAddr + kk * 32);
            uint32_t b[6][2];
#pragma unroll
            for (int np = 0; np < 3; np++)
                ldsm_x4t(b[2 * np][0], b[2 * np][1], b[2 * np + 1][0], b[2 * np + 1][1],
                         bAddr[np] + kk * 16 * WSTc * 2);
#pragma unroll
            for (int nf = 0; nf < 6; nf++) mma_bf16(ac2[nf], a, b[nf]);
        }

        const int row = rowBase + m0 + lr;
        const int b0 = row >> 14, q0 = row & 16383;
#pragma unroll
        for (int nf = 0; nf < 6; nf++) {
            const int col = n0 + nf * 8 + lc;
            const float2 bb = (col < 64) ? *(const float2*)(b_off + col)
                                         : *(const float2*)(b_attn + col - 64);
            int h, jj;
            if (col < 64) { h = col >> 3; jj = col & 7; }
            else          { h = (col - 64) >> 2; jj = 8 + ((col - 64) & 3); }
            const size_t base = (size_t)(b0 * 8 + h) * NQ;
            *(float2*)(g_offattn + (base + q0) * 12 + jj) =
                make_float2(ac2[nf][0] + bb.x, ac2[nf][1] + bb.y);
            *(float2*)(g_offattn + (base + q0 + 8) * 12 + jj) =
                make_float2(ac2[nf][2] + bb.x, ac2[nf][3] + bb.y);
        }
    }
}

// ---------------------------------------------------------------------------
// FUSED gather + output GEMM. Block = (batch, 8x8 query tile), all 8 heads.
// smem: sv   8 heads x 16x16 pixels x 32B        = 65,536 B
//       As   64 x AST bf16 (sampled matrix)       = 17,408 B
//       Ws   128 x WST64 bf16 (W_out col-half)    = 18,432 B   total 101,376 B
// Phases: fill (cp.async) || params+softmax -> gather 2 (q,h)/thread -> As
//         -> GEMM pass0 (cols 0..63) -> refill Ws || epilogue0 -> pass1.
// ---------------------------------------------------------------------------
#define SV_BYTES 65536
#define AS_BYTE_OFF 65536
#define WS_BYTE_OFF (65536 + 17408)
#define FUSED_SMEM (65536 + 17408 + 18432)

__global__ __launch_bounds__(256) void fused_gather_out(
    const float* __restrict__ bias,
    const float* __restrict__ query, float* __restrict__ C)
{
    extern __shared__ char smc[];
    const uint32_t svb = smem_u32(smc);
    const uint32_t asb = svb + AS_BYTE_OFF;
    const uint32_t wsb = svb + WS_BYTE_OFF;

    const int t   = threadIdx.x;
    const int blk = blockIdx.x;
    const int bt  = blk >> 8;          // batch
    const int til = blk & 255;
    const int x0  = (til & 15) * 8, y0 = (til >> 4) * 8;
    const int xlo = x0 - 4, ylo = y0 - 4;

    // --- issue Ws pass-0 fill (cols 0..63): 1024 x 16B ---
#pragma unroll
    for (int j = 0; j < 4; j++) {
        const int idx = t + j * 256;
        const int row = idx >> 3, c8 = idx & 7;
        cp_async16(wsb + (row * WST64 + c8 * 8) * 2, g_Wout16 + row * 128 + c8 * 8);
    }
    // --- issue value-tile fills: 8 heads x 16x16 pixels x 2 chunks = 4096 x 16B ---
#pragma unroll
    for (int j = 0; j < 16; j++) {
        const int idx = t + j * 256;
        const int hh  = idx >> 9;
        const int rest = idx & 511;
        const int pix = rest >> 1, jj = rest & 1;
        const int py = pix >> 4, px = pix & 15;
        const int gy = ylo + py, gx = xlo + px;
        const int slot = jj ^ ((px >> 2) & 1);
        const uint32_t dst = svb + (hh * 256 + pix) * 32 + slot * 16;
        if ((unsigned)gy < 128u && (unsigned)gx < 128u) {
            cp_async16(dst, g_value + ((size_t)(bt * 8 + hh) * NQ + gy * BEV + gx) * 16 + jj * 8);
        } else {
            *(uint4*)(smc + (hh * 256 + pix) * 32 + slot * 16) = make_uint4(0u, 0u, 0u, 0u);
        }
    }
    cp_commit();

    // --- per-thread params for 2 (q,h) pairs (overlap the fills) ---
    const int ql = t & 63;
    const int h0 = t >> 6;             // 0..3 ; second pair h0+4
    const int qx = ql & 7, qy = ql >> 3;
    const int x = x0 + qx, y = y0 + qy;
    const int q = y * BEV + x;

    float off[2][8], aw[2][4];
#pragma unroll
    for (int p2 = 0; p2 < 2; p2++) {
        const int hh = h0 + p2 * 4;
        const float* oa = g_offattn + ((size_t)(bt * 8 + hh) * NQ + q) * 12;
        const float4 A0 = *(const float4*)(oa);
        const float4 A1 = *(const float4*)(oa + 4);
        const float4 A2 = *(const float4*)(oa + 8);
        off[p2][0] = A0.x; off[p2][1] = A0.y; off[p2][2] = A0.z; off[p2][3] = A0.w;
        off[p2][4] = A1.x; off[p2][5] = A1.y; off[p2][6] = A1.z; off[p2][7] = A1.w;
        float lg[4] = {A2.x, A2.y, A2.z, A2.w};
        const float mx = fmaxf(fmaxf(lg[0], lg[1]), fmaxf(lg[2], lg[3]));
        float s = 0.0f;
#pragma unroll
        for (int p = 0; p < 4; p++) { aw[p2][p] = __expf(lg[p] - mx); s += aw[p2][p]; }
        const float inv = 1.0f / s;
#pragma unroll
        for (int p = 0; p < 4; p++) aw[p2][p] *= inv;
    }

    const float scale = 128.0f / 127.0f;
    const float refx = (float)x * scale;
    const float refy = (float)y * scale;

    cp_wait_all();
    __syncthreads();

    // --- gather both pairs, write sampled rows into As ---
#pragma unroll
    for (int p2 = 0; p2 < 2; p2++) {
        const int hh = h0 + p2 * 4;
        const char* svh = smc + hh * 256 * 32;
        const __nv_bfloat16* vsrc = g_value + (size_t)(bt * 8 + hh) * NQ * 16;

        float2 acc[8];
#pragma unroll
        for (int j = 0; j < 8; j++) acc[j] = make_float2(0.f, 0.f);

#pragma unroll
        for (int p = 0; p < 4; p++) {
            const float px = refx + off[p2][p * 2 + 0] - 0.5f;
            const float py = refy + off[p2][p * 2 + 1] - 0.5f;
            const float x0f = floorf(px), y0f = floorf(py);
            const int cx0 = (int)x0f, cy0 = (int)y0f;
            const float wx = px - x0f, wy = py - y0f;
            const float w = aw[p2][p];
            const float cws[4] = {w * (1.f - wx) * (1.f - wy), w * wx * (1.f - wy),
                                  w * (1.f - wx) * wy,         w * wx * wy};
            const int xs[4] = {cx0, cx0 + 1, cx0, cx0 + 1};
            const int ys[4] = {cy0, cy0, cy0 + 1, cy0 + 1};
#pragma unroll
            for (int c = 0; c < 4; c++) {
                const int xi = xs[c], yi = ys[c];
                const int sx = xi - xlo, sy = yi - ylo;
                const float cw = cws[c];
                uint4 u0, u1;
                bool have = false;
                if ((unsigned)sx < 16u && (unsigned)sy < 16u) {
                    const char* pp = svh + (sy * 16 + sx) * 32;
                    const int sw = (sx >> 2) & 1;
                    u0 = *(const uint4*)(pp + (0 ^ sw) * 16);
                    u1 = *(const uint4*)(pp + (1 ^ sw) * 16);
                    have = true;
                } else if ((unsigned)xi < 128u && (unsigned)yi < 128u) {
                    const uint4* cp = (const uint4*)(vsrc + (size_t)(yi * BEV + xi) * 16);
                    u0 = cp[0]; u1 = cp[1];
                    have = true;
                }
                if (have) {
                    const uint32_t uu[8] = {u0.x, u0.y, u0.z, u0.w, u1.x, u1.y, u1.z, u1.w};
#pragma unroll
                    for (int j = 0; j < 8; j++) {
                        const float2 cv = __bfloat1622float2(*(const __nv_bfloat162*)&uu[j]);
                        acc[j].x = fmaf(cw, cv.x, acc[j].x);
                        acc[j].y = fmaf(cw, cv.y, acc[j].y);
                    }
                }
            }
        }

        uint32_t ov[8];
#pragma unroll
        for (int j = 0; j < 8; j++) {
            const __nv_bfloat162 bv = __floats2bfloat162_rn(acc[j].x, acc[j].y);
            ov[j] = *(const uint32_t*)&bv;
        }
        char* asp = smc + AS_BYTE_OFF + (ql * AST + hh * 16) * 2;
        *(uint4*)(asp)      = make_uint4(ov[0], ov[1], ov[2], ov[3]);
        *(uint4*)(asp + 16) = make_uint4(ov[4], ov[5], ov[6], ov[7]);
    }
    __syncthreads();

    // --- GEMM: out[64x128] = As @ W_out + bias + 2*query, two 64-col passes ---
    const int wid = t >> 5, lane = t & 31;
    const int wm = wid & 3, wn = wid >> 2;
    const int m0 = wm * 16;
    const int n0 = wn * 32;
    const uint32_t aAddr = asb + ((m0 + (lane & 15)) * AST + (lane >> 4) * 8) * 2;
    const int kOff = ((lane >> 3) & 1) * 8 + (lane & 7);
    const int cOff = ((lane >> 4) & 1) * 8;
    const int lr = lane >> 2, lc = (lane & 3) * 2;
    const int ybase = y0 + (m0 >> 3);
    const int mrow0 = bt * NQ + ybase * BEV + x0 + lr;   // row for acc[..][0,1]

    uint32_t bAddr[2];
#pragma unroll
    for (int np = 0; np < 2; np++)
        bAddr[np] = wsb + (kOff * WST64 + n0 + np * 16 + cOff) * 2;

#pragma unroll
    for (int pass = 0; pass < 2; pass++) {
        float acc[4][4];
#pragma unroll
        for (int nf = 0; nf < 4; nf++)
#pragma unroll
            for (int i = 0; i < 4; i++) acc[nf][i] = 0.0f;

#pragma unroll
        for (int kk = 0; kk < 8; kk++) {
            uint32_t a[4];
            ldsm_x4(a[0], a[1], a[2], a[3], aAddr + kk * 32);
            uint32_t b[4][2];
#pragma unroll
            for (int np = 0; np < 2; np++)
                ldsm_x4t(b[2 * np][0], b[2 * np][1], b[2 * np + 1][0], b[2 * np + 1][1],
                         bAddr[np] + kk * 16 * WST64 * 2);
#pragma unroll
            for (int nf = 0; nf < 4; nf++) mma_bf16(acc[nf], a, b[nf]);
        }

        if (pass == 0) {
            // refill Ws with cols 64..127 while doing epilogue
            __syncthreads();
#pragma unroll
            for (int j = 0; j < 4; j++) {
                const int idx = t + j * 256;
                const int row = idx >> 3, c8 = idx & 7;
                cp_async16(wsb + (row * WST64 + c8 * 8) * 2,
                           g_Wout16 + row * 128 + 64 + c8 * 8);
            }
            cp_commit();
        }

        const int colB = pass * 64;
#pragma unroll
        for (int nf = 0; nf < 4; nf++) {
            const int col = colB + n0 + nf * 8 + lc;
            const float2 bb = *(const float2*)(bias + col);
            const float2 r0 = *(const float2*)(query + (size_t)mrow0 * EMB + col);
            const float2 r1 = *(const float2*)(query + (size_t)(mrow0 + BEV) * EMB + col);
            *(float2*)(C + (size_t)mrow0 * EMB + col) =
                make_float2(acc[nf][0] + bb.x + 2.0f * r0.x, acc[nf][1] + bb.y + 2.0f * r0.y);
            *(float2*)(C + (size_t)(mrow0 + BEV) * EMB + col) =
                make_float2(acc[nf][2] + bb.x + 2.0f * r1.x, acc[nf][3] + bb.y + 2.0f * r1.y);
        }

        if (pass == 0) {
            cp_wait_all();
            __syncthreads();
        }
    }
}

// ---------------------------------------------------------------------------

extern "C" void kernel_launch(void* const* d_in, const int* in_sizes, int n_in,
                              void* d_out, int out_size)
{
    const float* query  = (const float*)d_in[0];
    const float* W_off  = (const float*)d_in[1];
    const float* b_off  = (const float*)d_in[2];
    const float* W_attn = (const float*)d_in[3];
    const float* b_attn = (const float*)d_in[4];
    const float* W_val  = (const float*)d_in[5];
    const float* b_val  = (const float*)d_in[6];
    const float* W_out  = (const float*)d_in[7];
    const float* b_out  = (const float*)d_in[8];
    float* out = (float*)d_out;

    cudaFuncSetAttribute(fused_gather_out,
                         cudaFuncAttributeMaxDynamicSharedMemorySize, FUSED_SMEM);

    // 0) one-shot weight conversion to bf16
    conv_kernel<<<176, 256>>>(W_val, W_out, W_off, W_attn);

    // 1) fused value + offset/attn projections (64-row tiles, 1024 CTAs)
    proj_kernel<<<M_TOTAL / 64, 256>>>(query, b_val, b_off, b_attn);

    // 2) fused gather + output projection (1024 CTAs, 2/SM)
    fused_gather_out<<<BS * 256, 256, FUSED_SMEM>>>(b_out, query, out);
}

// round 17
// speedup vs baseline: 1.0805x; 1.0805x over previous
#include <cuda_runtime.h>
#include <cuda_bf16.h>
#include <cstdint>

#define BS 4
#define NQ 16384
#define EMB 128
#define NH 8
#define NP 4
#define HD 16
#define BEV 128
#define M_TOTAL (BS * NQ)   // 65536

// Scratch (device globals: allocation-guard safe)
__device__ __nv_bfloat16 g_value[M_TOTAL * EMB];    // head-major: ((b*8+h)*NQ+q)*16+d
__device__ __nv_bfloat16 g_offattn[M_TOTAL * 96];   // ((b*8+h)*NQ+q)*12 bf16: 8 off + 4 logits
__device__ __nv_bfloat16 g_sampled[M_TOTAL * EMB];  // head-major like g_value
__device__ __nv_bfloat16 g_Wval16[128 * 128];
__device__ __nv_bfloat16 g_Wout16[128 * 128];
__device__ __nv_bfloat16 g_Wcat16[128 * 96];        // [W_off | W_attn]

// ---------------------------------------------------------------------------
// helpers
// ---------------------------------------------------------------------------
__device__ __forceinline__ uint32_t smem_u32(const void* p) {
    return (uint32_t)__cvta_generic_to_shared(p);
}
__device__ __forceinline__ void ldsm_x4(uint32_t& r0, uint32_t& r1, uint32_t& r2,
                                        uint32_t& r3, uint32_t addr) {
    asm volatile("ldmatrix.sync.aligned.m8n8.x4.shared.b16 {%0,%1,%2,%3},[%4];\n"
                 : "=r"(r0), "=r"(r1), "=r"(r2), "=r"(r3) : "r"(addr));
}
__device__ __forceinline__ void ldsm_x4t(uint32_t& r0, uint32_t& r1, uint32_t& r2,
                                         uint32_t& r3, uint32_t addr) {
    asm volatile("ldmatrix.sync.aligned.m8n8.x4.trans.shared.b16 {%0,%1,%2,%3},[%4];\n"
                 : "=r"(r0), "=r"(r1), "=r"(r2), "=r"(r3) : "r"(addr));
}
__device__ __forceinline__ void mma_bf16(float* d, const uint32_t* a,
                                         const uint32_t* b) {
    asm volatile(
        "mma.sync.aligned.m16n8k16.row.col.f32.bf16.bf16.f32 "
        "{%0,%1,%2,%3},{%4,%5,%6,%7},{%8,%9},{%0,%1,%2,%3};\n"
        : "+f"(d[0]), "+f"(d[1]), "+f"(d[2]), "+f"(d[3])
        : "r"(a[0]), "r"(a[1]), "r"(a[2]), "r"(a[3]), "r"(b[0]), "r"(b[1]));
}
__device__ __forceinline__ void cp_async16(uint32_t saddr, const void* g) {
    asm volatile("cp.async.ca.shared.global [%0], [%1], 16;\n" :: "r"(saddr), "l"(g));
}
__device__ __forceinline__ void cp_commit() {
    asm volatile("cp.async.commit_group;\n" ::: "memory");
}
__device__ __forceinline__ void cp_wait_all() {
    asm volatile("cp.async.wait_group 0;\n" ::: "memory");
}

#define AST 136   // A/Wval smem row stride (bf16)

// ---------------------------------------------------------------------------
// One-shot weight conversion fp32 -> bf16 (+ pack W_off|W_attn)
// ---------------------------------------------------------------------------
__global__ __launch_bounds__(256) void conv_kernel(
    const float* __restrict__ W_val, const float* __restrict__ W_out,
    const float* __restrict__ W_off, const float* __restrict__ W_attn)
{
    const int i = blockIdx.x * 256 + threadIdx.x;   // 176 blocks
    if (i < 16384) {
        g_Wval16[i] = __float2bfloat16(W_val[i]);
        g_Wout16[i] = __float2bfloat16(W_out[i]);
    } else {
        const int j = i - 16384;
        if (j < 12288) {
            const int k = j / 96, c = j % 96;
            const float v = (c < 64) ? W_off[k * 64 + c] : W_attn[k * 32 + (c - 64)];
            g_Wcat16[j] = __float2bfloat16(v);
        }
    }
}

// ---------------------------------------------------------------------------
// Fused projection kernel: 64-row one-shot tile per CTA.
//   1) value = q @ W_val + b_val          -> g_value (bf16 head-major)
//   2) offattn = q @ [W_off|W_attn] + b   -> g_offattn (12 bf16 per (b,h,q))
// ---------------------------------------------------------------------------
__global__ __launch_bounds__(256) void proj_kernel(
    const float* __restrict__ query,
    const float* __restrict__ b_val,
    const float* __restrict__ b_off, const float* __restrict__ b_attn)
{
    __shared__ __nv_bfloat16 As[64 * AST];
    __shared__ __nv_bfloat16 Ws[128 * AST];

    const int t = threadIdx.x;
    const int rowBase = blockIdx.x * 64;
    const uint32_t asb = smem_u32(As);
    const uint32_t wsb = smem_u32(Ws);

    // --- W_val tile via cp.async (2048 x 16B) ---
#pragma unroll
    for (int j = 0; j < 8; j++) {
        const int idx = t + j * 256;
        const int row = idx >> 4, c8 = idx & 15;
        cp_async16(wsb + (row * AST + c8 * 8) * 2, g_Wval16 + row * 128 + c8 * 8);
    }
    cp_commit();

    // --- A tile: 64x128 fp32 -> bf16 (overlaps cp.async) ---
#pragma unroll
    for (int j = 0; j < 8; j++) {
        const int idx = t + j * 256;
        const int row = idx >> 5, c4 = idx & 31;
        float4 v = *(const float4*)(query + (size_t)(rowBase + row) * EMB + c4 * 4);
        *(__nv_bfloat162*)(As + row * AST + c4 * 4)     = __floats2bfloat162_rn(v.x, v.y);
        *(__nv_bfloat162*)(As + row * AST + c4 * 4 + 2) = __floats2bfloat162_rn(v.z, v.w);
    }
    cp_wait_all();
    __syncthreads();

    const int wid = t >> 5, lane = t & 31;
    const int wm = wid & 3, wn = wid >> 2;
    const int m0 = wm * 16;
    const uint32_t aAddr = asb + ((m0 + (lane & 15)) * AST + (lane >> 4) * 8) * 2;
    const int kOff = ((lane >> 3) & 1) * 8 + (lane & 7);
    const int cOff = ((lane >> 4) & 1) * 8;
    const int lr = lane >> 2, lc = (lane & 3) * 2;

    // ===== part 1: value (N=128, warp n-tile 64, NF=8) =====
    float acc[8][4];
    {
        const int n0 = wn * 64;
#pragma unroll
        for (int nf = 0; nf < 8; nf++)
#pragma unroll
            for (int i = 0; i < 4; i++) acc[nf][i] = 0.0f;
        uint32_t bAddr[4];
#pragma unroll
        for (int np = 0; np < 4; np++)
            bAddr[np] = wsb + (kOff * AST + n0 + np * 16 + cOff) * 2;

#pragma unroll
        for (int kk = 0; kk < 8; kk++) {
            uint32_t a[4];
            ldsm_x4(a[0], a[1], a[2], a[3], aAddr + kk * 32);
            uint32_t b[8][2];
#pragma unroll
            for (int np = 0; np < 4; np++)
                ldsm_x4t(b[2 * np][0], b[2 * np][1], b[2 * np + 1][0], b[2 * np + 1][1],
                         bAddr[np] + kk * 16 * AST * 2);
#pragma unroll
            for (int nf = 0; nf < 8; nf++) mma_bf16(acc[nf], a, b[nf]);
        }
    }
    __syncthreads();   // all warps done reading Ws

    // --- issue W_cat cp.async (1536 x 16B), then do part-1 epilogue ---
    constexpr int WSTc = 104;
#pragma unroll
    for (int j = 0; j < 6; j++) {
        const int idx = t + j * 256;
        const int row = idx / 12, c8 = idx % 12;
        cp_async16(wsb + (row * WSTc + c8 * 8) * 2, g_Wcat16 + row * 96 + c8 * 8);
    }
    cp_commit();

    {
        const int n0 = wn * 64;
        const int row = rowBase + m0 + lr;
        const int b0 = row >> 14, q0 = row & 16383;
#pragma unroll
        for (int nf = 0; nf < 8; nf++) {
            const int col = n0 + nf * 8 + lc;
            const float2 bb = *(const float2*)(b_val + col);
            const int h = col >> 4, d = col & 15;
            const size_t base = (size_t)(b0 * 8 + h) * NQ;
            *(__nv_bfloat162*)(g_value + (base + q0) * 16 + d) =
                __floats2bfloat162_rn(acc[nf][0] + bb.x, acc[nf][1] + bb.y);
            *(__nv_bfloat162*)(g_value + (base + q0 + 8) * 16 + d) =
                __floats2bfloat162_rn(acc[nf][2] + bb.x, acc[nf][3] + bb.y);
        }
    }
    cp_wait_all();
    __syncthreads();

    // ===== part 2: offattn (N=96, warp n-tile 48, NF=6) -> bf16 =====
    {
        const int n0 = wn * 48;
        float ac2[6][4];
#pragma unroll
        for (int nf = 0; nf < 6; nf++)
#pragma unroll
            for (int i = 0; i < 4; i++) ac2[nf][i] = 0.0f;
        uint32_t bAddr[3];
#pragma unroll
        for (int np = 0; np < 3; np++)
            bAddr[np] = wsb + (kOff * WSTc + n0 + np * 16 + cOff) * 2;

#pragma unroll
        for (int kk = 0; kk < 8; kk++) {
            uint32_t a[4];
            ldsm_x4(a[0], a[1], a[2], a[3], aAddr + kk * 32);
            uint32_t b[6][2];
#pragma unroll
            for (int np = 0; np < 3; np++)
                ldsm_x4t(b[2 * np][0], b[2 * np][1], b[2 * np + 1][0], b[2 * np + 1][1],
                         bAddr[np] + kk * 16 * WSTc * 2);
#pragma unroll
            for (int nf = 0; nf < 6; nf++) mma_bf16(ac2[nf], a, b[nf]);
        }

        const int row = rowBase + m0 + lr;
        const int b0 = row >> 14, q0 = row & 16383;
#pragma unroll
        for (int nf = 0; nf < 6; nf++) {
            const int col = n0 + nf * 8 + lc;
            const float2 bb = (col < 64) ? *(const float2*)(b_off + col)
                                         : *(const float2*)(b_attn + col - 64);
            int h, jj;
            if (col < 64) { h = col >> 3; jj = col & 7; }
            else          { h = (col - 64) >> 2; jj = 8 + ((col - 64) & 3); }
            const size_t base = (size_t)(b0 * 8 + h) * NQ;
            *(__nv_bfloat162*)(g_offattn + (base + q0) * 12 + jj) =
                __floats2bfloat162_rn(ac2[nf][0] + bb.x, ac2[nf][1] + bb.y);
            *(__nv_bfloat162*)(g_offattn + (base + q0 + 8) * 12 + jj) =
                __floats2bfloat162_rn(ac2[nf][2] + bb.x, ac2[nf][3] + bb.y);
        }
    }
}

// ---------------------------------------------------------------------------
// Output GEMM, 64x64 tiles (2048 CTAs). Epilogue operands (bias + 2*query)
// PREFETCHED before the mainloop so their DRAM latency hides under the mmas.
// ---------------------------------------------------------------------------
#define WST64 72
__global__ __launch_bounds__(256) void out_gemm(
    const float* __restrict__ bias,
    const float* __restrict__ query, float* __restrict__ C)
{
    __shared__ __nv_bfloat16 As[64 * AST];
    __shared__ __nv_bfloat16 Ws[128 * WST64];

    const int t = threadIdx.x;
    const int tile  = blockIdx.x >> 1;
    const int nhalf = blockIdx.x & 1;
    const int rowBase = tile * 64;
    const int colBase = nhalf * 64;
    const uint32_t asb = smem_u32(As);
    const uint32_t wsb = smem_u32(Ws);

    // --- A tile (1024 x 16B) via cp.async from bf16 head-major ---
#pragma unroll
    for (int j = 0; j < 4; j++) {
        const int idx = t + j * 256;
        const int row = idx >> 4, c8 = idx & 15;
        const int h = c8 >> 1, d = (c8 & 1) * 8;
        const int gr = rowBase + row;
        const int b0 = gr >> 14, q0 = gr & 16383;
        cp_async16(asb + (row * AST + c8 * 8) * 2,
                   g_sampled + ((size_t)(b0 * 8 + h) * NQ + q0) * 16 + d);
    }
    // --- W half tile (1024 x 16B) ---
#pragma unroll
    for (int j = 0; j < 4; j++) {
        const int idx = t + j * 256;
        const int row = idx >> 3, c8 = idx & 7;
        cp_async16(wsb + (row * WST64 + c8 * 8) * 2,
                   g_Wout16 + row * 128 + colBase + c8 * 8);
    }
    cp_commit();

    const int wid = t >> 5, lane = t & 31;
    const int wm = wid & 3, wn = wid >> 2;
    const int m0 = wm * 16;
    const int n0 = wn * 32;
    const int lr = lane >> 2, lc = (lane & 3) * 2;
    const int row = rowBase + m0 + lr;

    // --- PREFETCH epilogue operands (overlap cp.async fills + mainloop) ---
    float2 pb[4], pq0[4], pq1[4];
#pragma unroll
    for (int nf = 0; nf < 4; nf++) {
        const int col = colBase + n0 + nf * 8 + lc;
        pb[nf]  = *(const float2*)(bias + col);
        pq0[nf] = *(const float2*)(query + (size_t)row * EMB + col);
        pq1[nf] = *(const float2*)(query + (size_t)(row + 8) * EMB + col);
    }

    cp_wait_all();
    __syncthreads();

    const uint32_t aAddr = asb + ((m0 + (lane & 15)) * AST + (lane >> 4) * 8) * 2;
    const int kOff = ((lane >> 3) & 1) * 8 + (lane & 7);
    const int cOff = ((lane >> 4) & 1) * 8;

    float acc[4][4];
#pragma unroll
    for (int nf = 0; nf < 4; nf++)
#pragma unroll
        for (int i = 0; i < 4; i++) acc[nf][i] = 0.0f;
    uint32_t bAddr[2];
#pragma unroll
    for (int np = 0; np < 2; np++)
        bAddr[np] = wsb + (kOff * WST64 + n0 + np * 16 + cOff) * 2;

#pragma unroll
    for (int kk = 0; kk < 8; kk++) {
        uint32_t a[4];
        ldsm_x4(a[0], a[1], a[2], a[3], aAddr + kk * 32);
        uint32_t b[4][2];
#pragma unroll
        for (int np = 0; np < 2; np++)
            ldsm_x4t(b[2 * np][0], b[2 * np][1], b[2 * np + 1][0], b[2 * np + 1][1],
                     bAddr[np] + kk * 16 * WST64 * 2);
#pragma unroll
        for (int nf = 0; nf < 4; nf++) mma_bf16(acc[nf], a, b[nf]);
    }

#pragma unroll
    for (int nf = 0; nf < 4; nf++) {
        const int col = colBase + n0 + nf * 8 + lc;
        *(float2*)(C + (size_t)row * EMB + col) =
            make_float2(acc[nf][0] + pb[nf].x + 2.0f * pq0[nf].x,
                        acc[nf][1] + pb[nf].y + 2.0f * pq0[nf].y);
        *(float2*)(C + (size_t)(row + 8) * EMB + col) =
            make_float2(acc[nf][2] + pb[nf].x + 2.0f * pq1[nf].x,
                        acc[nf][3] + pb[nf].y + 2.0f * pq1[nf].y);
    }
}

// ---------------------------------------------------------------------------
// Tiled gather: block = (b, h, 16x16 query tile). 24x24 pixel x 16 bf16 tile
// filled via cp.async (zero STS for out-of-image); params read (bf16) overlaps
// the fill; softmax + bilinear in fp32; global fallback outside halo.
// ---------------------------------------------------------------------------
__global__ __launch_bounds__(256) void gather_kernel()
{
    __shared__ uint32_t sv[24 * 24 * 8];   // 18,432 B

    const int blk  = blockIdx.x;
    const int tile = blk & 63;
    const int h    = (blk >> 6) & 7;
    const int b    = blk >> 9;
    const int tx0  = (tile & 7) * 16, ty0 = (tile >> 3) * 16;
    const int xlo  = tx0 - 4, ylo = ty0 - 4;
    const int t    = threadIdx.x;
    const uint32_t svb = smem_u32(sv);

    const __nv_bfloat16* vsrc = g_value + (size_t)(b * 8 + h) * NQ * 16;

    // --- fill smem tile via cp.async: 1152 16B chunks ---
#pragma unroll
    for (int ii = 0; ii < 5; ii++) {
        const int i = t + ii * 256;
        if (i < 1152) {
            const int pix = i >> 1, j = i & 1;
            const int py = pix / 24, px = pix - py * 24;
            const int gy = ylo + py, gx = xlo + px;
            const int slot = j ^ ((px >> 2) & 1);
            if ((unsigned)gy < 128u && (unsigned)gx < 128u) {
                cp_async16(svb + pix * 32 + slot * 16,
                           vsrc + (size_t)(gy * BEV + gx) * 16 + j * 8);
            } else {
                *(uint4*)((char*)sv + pix * 32 + slot * 16) = make_uint4(0u, 0u, 0u, 0u);
            }
        }
    }
    cp_commit();

    // --- per-thread parameters (bf16, 24B/thread, overlaps fill) ---
    const int x = tx0 + (t & 15), y = ty0 + (t >> 4);
    const int q = y * BEV + x;
    const __nv_bfloat16* oa = g_offattn + ((size_t)(b * 8 + h) * NQ + q) * 12;
    const uint2 u01 = *(const uint2*)(oa);
    const uint2 u23 = *(const uint2*)(oa + 4);
    const uint2 ulg = *(const uint2*)(oa + 8);
    float off[8], lg[4];
    {
        const float2 f0 = __bfloat1622float2(*(const __nv_bfloat162*)&u01.x);
        const float2 f1 = __bfloat1622float2(*(const __nv_bfloat162*)&u01.y);
        const float2 f2 = __bfloat1622float2(*(const __nv_bfloat162*)&u23.x);
        const float2 f3 = __bfloat1622float2(*(const __nv_bfloat162*)&u23.y);
        off[0] = f0.x; off[1] = f0.y; off[2] = f1.x; off[3] = f1.y;
        off[4] = f2.x; off[5] = f2.y; off[6] = f3.x; off[7] = f3.y;
        const float2 l0 = __bfloat1622float2(*(const __nv_bfloat162*)&ulg.x);
        const float2 l1 = __bfloat1622float2(*(const __nv_bfloat162*)&ulg.y);
        lg[0] = l0.x; lg[1] = l0.y; lg[2] = l1.x; lg[3] = l1.y;
    }

    // softmax over points (overlaps fill)
    const float mx = fmaxf(fmaxf(lg[0], lg[1]), fmaxf(lg[2], lg[3]));
    float aw[4], s = 0.0f;
#pragma unroll
    for (int p = 0; p < 4; p++) { aw[p] = __expf(lg[p] - mx); s += aw[p]; }
    const float inv = 1.0f / s;
#pragma unroll
    for (int p = 0; p < 4; p++) aw[p] *= inv;

    cp_wait_all();
    __syncthreads();

    const float scale = 128.0f / 127.0f;
    const float refx = (float)x * scale;
    const float refy = (float)y * scale;

    float2 acc[8];
#pragma unroll
    for (int j = 0; j < 8; j++) acc[j] = make_float2(0.f, 0.f);

#pragma unroll
    for (int p = 0; p < 4; p++) {
        const float px = refx + off[p * 2 + 0] - 0.5f;
        const float py = refy + off[p * 2 + 1] - 0.5f;
        const float x0f = floorf(px), y0f = floorf(py);
        const int x0 = (int)x0f, y0 = (int)y0f;
        const float wx = px - x0f, wy = py - y0f;
        const float w = aw[p];
        const float cws[4] = {w * (1.f - wx) * (1.f - wy), w * wx * (1.f - wy),
                              w * (1.f - wx) * wy,         w * wx * wy};
        const int xs[4] = {x0, x0 + 1, x0, x0 + 1};
        const int ys[4] = {y0, y0, y0 + 1, y0 + 1};
#pragma unroll
        for (int c = 0; c < 4; c++) {
            const int xi = xs[c], yi = ys[c];
            const int sx = xi - xlo, sy = yi - ylo;
            const float cw = cws[c];
            uint4 u0, u1;
            bool have = false;
            if ((unsigned)sx < 24u && (unsigned)sy < 24u) {
                const uint32_t* pp = sv + (sy * 24 + sx) * 8;
                const int sw = (sx >> 2) & 1;
                u0 = *(const uint4*)(pp + (0 ^ sw) * 4);
                u1 = *(const uint4*)(pp + (1 ^ sw) * 4);
                have = true;
            } else if ((unsigned)xi < 128u && (unsigned)yi < 128u) {
                const uint4* cp = (const uint4*)(vsrc + (size_t)(yi * BEV + xi) * 16);
                u0 = cp[0]; u1 = cp[1];
                have = true;
            }
            if (have) {
                const uint32_t uu[8] = {u0.x, u0.y, u0.z, u0.w, u1.x, u1.y, u1.z, u1.w};
#pragma unroll
                for (int j = 0; j < 8; j++) {
                    const float2 cv = __bfloat1622float2(*(const __nv_bfloat162*)&uu[j]);
                    acc[j].x = fmaf(cw, cv.x, acc[j].x);
                    acc[j].y = fmaf(cw, cv.y, acc[j].y);
                }
            }
        }
    }

    __nv_bfloat16* outp = g_sampled + ((size_t)(b * 8 + h) * NQ + q) * 16;
    uint32_t ov[8];
#pragma unroll
    for (int j = 0; j < 8; j++) {
        const __nv_bfloat162 bv = __floats2bfloat162_rn(acc[j].x, acc[j].y);
        ov[j] = *(const uint32_t*)&bv;
    }
    *(uint4*)(outp)     = make_uint4(ov[0], ov[1], ov[2], ov[3]);
    *(uint4*)(outp + 8) = make_uint4(ov[4], ov[5], ov[6], ov[7]);
}

// ---------------------------------------------------------------------------

extern "C" void kernel_launch(void* const* d_in, const int* in_sizes, int n_in,
                              void* d_out, int out_size)
{
    const float* query  = (const float*)d_in[0];
    const float* W_off  = (const float*)d_in[1];
    const float* b_off  = (const float*)d_in[2];
    const float* W_attn = (const float*)d_in[3];
    const float* b_attn = (const float*)d_in[4];
    const float* W_val  = (const float*)d_in[5];
    const float* b_val  = (const float*)d_in[6];
    const float* W_out  = (const float*)d_in[7];
    const float* b_out  = (const float*)d_in[8];
    float* out = (float*)d_out;

    // 0) one-shot weight conversion to bf16
    conv_kernel<<<176, 256>>>(W_val, W_out, W_off, W_attn);

    // 1) fused value + offset/attn projections (64-row tiles, 1024 CTAs)
    proj_kernel<<<M_TOTAL / 64, 256>>>(query, b_val, b_off, b_attn);

    // 2) tiled softmax + bilinear gather (cp.async fill)
    gather_kernel<<<BS * NH * 64, 256>>>();

    // 3) output projection, 64x64 tiles (2048 CTAs), prefetched epilogue
    out_gemm<<<M_TOTAL / 64 * 2, 256>>>(b_out, query, out);
}